// round 14
// baseline (speedup 1.0000x reference)
#include <cuda_runtime.h>
#include <cuda_fp16.h>
#include <cstdint>

#define Hh 128
#define Ww 128
#define LL 16384          // H*W
#define NB 2
#define NC1 64
#define NC2 128
#define OUT_LV2_ELEMS 4194304
#define SENT 16384        // sentinel tap offset -> zero slot

// Scratch
__device__ unsigned short g_tab[NB * 9 * LL];                  // 576 KB tap offsets
__device__ uint2          g_blkh[(size_t)NB * (LL + 1) * 64];  // 16.8 MB lv1 half4 blocks
__device__ unsigned       g_l2h[(size_t)NB * (LL + 1) * 64];   // 8.4 MB lv2 pixel-major half2
                                                               // word w of pixel p = ch (2w, 2w+1)

// ---------------------------------------------------------------------------
// k_tab: tap-offset table straight from hw (dtype sniff inline) + sentinel
// zeroing of g_blkh and g_l2h. 32 blocks, ~2us.
// ---------------------------------------------------------------------------
__global__ void k_tab(const int* __restrict__ hw) {
    __shared__ int s_or;
    int tid = threadIdx.x;
    if (tid == 0) s_or = 0;
    __syncthreads();
    int acc = 0;
#pragma unroll
    for (int k = 0; k < 8; k++) acc |= hw[2 * (tid + (k << 8)) + 1];
    if (acc) atomicOr(&s_or, 1);
    __syncthreads();
    int stride = s_or ? 1 : 2;                // int32 vs int64 source

    if (blockIdx.x == 0 && tid < 128) {       // zero sentinel cells
        int b = tid >> 6, c = tid & 63;
        g_blkh[((size_t)b * (LL + 1) + LL) * 64 + c] = make_uint2(0u, 0u);
        g_l2h[((size_t)b * (LL + 1) + LL) * 64 + c] = 0u;
    }

#pragma unroll
    for (int k = 0; k < 4; k++) {
        int gp = (blockIdx.x << 10) + (k << 8) + tid;   // 0..32767
        int b  = gp >> 14;
        int p  = gp & (LL - 1);
        int y = p >> 7, x = p & 127;
        unsigned short* tp = g_tab + (size_t)b * 9 * LL;
#pragma unroll
        for (int dy = -1; dy <= 1; dy++) {
#pragma unroll
            for (int dx = -1; dx <= 1; dx++) {
                int tap = (dy + 1) * 3 + (dx + 1);
                int oy = y - dy, ox = x - dx;
                unsigned short off = SENT;
                if ((unsigned)oy < Hh && (unsigned)ox < Ww) {
                    int m  = hw[((b << 14) + (oy << 7) + ox) * stride];
                    int sr = (m >> 7)  + dy;
                    int sc = (m & 127) + dx;
                    if ((unsigned)sr < Hh && (unsigned)sc < Ww)
                        off = (unsigned short)((sr << 7) + sc);
                }
                tp[tap * LL + p] = off;
            }
        }
    }
}

// ---------------------------------------------------------------------------
// k_blk: space-to-depth fp16 transpose of lv1 -> g_blkh (DRAM-streaming).
// ---------------------------------------------------------------------------
__global__ void k_blk(const float* __restrict__ lv1) {
    __shared__ uint2 s2h[64 * 33];
    unsigned* sw = (unsigned*)s2h;
    int bid = blockIdx.x;                     // 1024: (b, mh, vtile)
    int tid = threadIdx.x;
    int vt = bid & 3;
    int mh = (bid >> 2) & 127;
    int b  = bid >> 9;
    int v0 = vt << 5;

#pragma unroll
    for (int k = 0; k < 8; k++) {
        int j  = tid + (k << 8);
        int c  = j >> 5;
        int dy = (j >> 4) & 1;
        int x4 = j & 15;
        const float4 val = __ldcs((const float4*)(lv1 + (((size_t)(b * NC1 + c)) << 16)
                                                  + ((2 * mh + dy) << 8) + (v0 << 1) + (x4 << 2)));
        int vl0 = x4 << 1;
        __half2 h0 = __floats2half2_rn(val.x, val.y);
        __half2 h1 = __floats2half2_rn(val.z, val.w);
        sw[(c * 33 + vl0    ) * 2 + dy] = *(unsigned*)&h0;
        sw[(c * 33 + vl0 + 1) * 2 + dy] = *(unsigned*)&h1;
    }
    __syncthreads();

    uint2* dst = g_blkh + ((size_t)b * (LL + 1) + (mh << 7) + v0) * 64;
#pragma unroll
    for (int k = 0; k < 8; k++) {
        int j  = tid + (k << 8);
        int vl = j >> 6;
        int c  = j & 63;
        dst[(size_t)vl * 64 + c] = s2h[c * 33 + vl];
    }
}

// ---------------------------------------------------------------------------
// k_l2t: transpose lv2 [b][c][p] fp32 -> g_l2h [b][p][c] fp16 (pixel-major
// 256B records). Grid 256: (b, 128-px tile). SMEM-staged, padded pitch.
// ---------------------------------------------------------------------------
__global__ void k_l2t(const float* __restrict__ lv2) {
    __shared__ __half s[128 * 132];           // [c][px] pitch 132 halves
    int bid = blockIdx.x;
    int b  = bid >> 7;
    int pt = bid & 127;
    int p0 = pt << 7;
    int tid = threadIdx.x;

    // Read phase: 128 c-rows x 128 px fp32, coalesced 512B per c-row chunk.
#pragma unroll
    for (int k = 0; k < 16; k++) {
        int c  = (tid >> 5) + (k << 3);
        int x4 = tid & 31;
        const float4 v = __ldcs((const float4*)(lv2 + (((size_t)(b * NC2 + c)) << 14)
                                                + p0 + (x4 << 2)));
        __half2 h0 = __floats2half2_rn(v.x, v.y);
        __half2 h1 = __floats2half2_rn(v.z, v.w);
        *(__half2*)&s[c * 132 + (x4 << 2)]     = h0;
        *(__half2*)&s[c * 132 + (x4 << 2) + 2] = h1;
    }
    __syncthreads();

    // Write phase: per pixel 128 halves = 64 words = 256B, coalesced.
    unsigned* dst = g_l2h + ((size_t)b * (LL + 1) + p0) * 64;
#pragma unroll
    for (int k = 0; k < 32; k++) {
        int px = (k << 2) + (tid >> 6);
        int wi = tid & 63;
        int c0 = wi << 1;
        __half2 hv = __halves2half2(s[c0 * 132 + px], s[(c0 + 1) * 132 + px]);
        dst[(size_t)px * 64 + wi] = *(unsigned*)&hv;
    }
}

// ---------------------------------------------------------------------------
// k_lv2g: lv2 gather as warp-coalesced L2 reads (replaces SMEM-plane design).
// Warp per pixel: 9 taps x 256B coalesced LDG.64 (lane = 4 channels), fp32
// accumulate, half2 staging, coalesced fp32 output stores.
// Grid 512: (b, y, xtile of 64 px). 256 threads, 8 warps x 8 px.
// ---------------------------------------------------------------------------
__global__ void __launch_bounds__(256) k_lv2g(float* __restrict__ out) {
    __shared__ __half2 s2[64 * 65];           // [cpair][px] pitch 65
    int bid = blockIdx.x;
    int xt = bid & 1;
    int y  = (bid >> 1) & 127;
    int b  = bid >> 8;
    int p0 = (y << 7) + (xt << 6);
    int w    = threadIdx.x >> 5;
    int lane = threadIdx.x & 31;
    const unsigned short* tb = g_tab + (size_t)b * 9 * LL;
    const uint2* src = (const uint2*)g_l2h + ((size_t)b * (LL + 1)) * 32 + lane;
    const float inv9 = 1.0f / 9.0f;

#pragma unroll
    for (int jj = 0; jj < 8; jj++) {
        int px = (w << 3) + jj;               // local pixel 0..63
        int p  = p0 + px;
        float a0 = 0.f, a1 = 0.f, a2 = 0.f, a3 = 0.f;   // ch 4l..4l+3
        {   // taps 0..4
            uint2 t[5];
#pragma unroll
            for (int tap = 0; tap < 5; tap++)
                t[tap] = src[((size_t)tb[tap * LL + p]) << 5];
#pragma unroll
            for (int tap = 0; tap < 5; tap++) {
                float2 f0 = __half22float2(*(__half2*)&t[tap].x);
                float2 f1 = __half22float2(*(__half2*)&t[tap].y);
                a0 += f0.x; a1 += f0.y; a2 += f1.x; a3 += f1.y;
            }
        }
        {   // taps 5..8
            uint2 t[4];
#pragma unroll
            for (int tap = 0; tap < 4; tap++)
                t[tap] = src[((size_t)tb[(5 + tap) * LL + p]) << 5];
#pragma unroll
            for (int tap = 0; tap < 4; tap++) {
                float2 f0 = __half22float2(*(__half2*)&t[tap].x);
                float2 f1 = __half22float2(*(__half2*)&t[tap].y);
                a0 += f0.x; a1 += f0.y; a2 += f1.x; a3 += f1.y;
            }
        }
        // rows q=2l -> ch(4l,4l+1), q=2l+1 -> ch(4l+2,4l+3); 2-way banks max
        s2[(2 * lane    ) * 65 + px] = __floats2half2_rn(a0 * inv9, a1 * inv9);
        s2[(2 * lane + 1) * 65 + px] = __floats2half2_rn(a2 * inv9, a3 * inv9);
    }
    __syncthreads();

    // Copy-out: row q holds channels (2q, 2q+1); coalesced 128B fp32 stores.
    float* outb = out + (((size_t)b * NC2) << 14) + p0;
    for (int q = w; q < 64; q += 8) {
        float* r0 = outb + (((size_t)(q << 1)) << 14);
        float* r1 = r0 + LL;
        float2 f0 = __half22float2(s2[q * 65 + lane]);
        float2 f1 = __half22float2(s2[q * 65 + lane + 32]);
        r0[lane]      = f0.x;  r1[lane]      = f0.y;
        r0[lane + 32] = f1.x;  r1[lane + 32] = f1.y;
    }
}

// ---------------------------------------------------------------------------
// k_lv1: full grid (512 blocks), runs solo. Warp-per-cell gather; lane = 2
// channels; taps in groups of 5+4; half2 output staging (33.3KB, 4 blocks/SM).
// ---------------------------------------------------------------------------
__global__ void __launch_bounds__(256, 4) k_lv1(float* __restrict__ out) {
    extern __shared__ __half2 shh[];          // 128 rows x 65 half2 = 33280 B
    int bid  = blockIdx.x;                    // 512: (b, u, vtile)
    int vt   = bid & 1;
    int u    = (bid >> 1) & 127;
    int b    = bid >> 8;
    int v0   = vt << 6;
    int w    = threadIdx.x >> 5;
    int lane = threadIdx.x & 31;
    const unsigned short* tb = g_tab + (size_t)b * 9 * LL;
    const uint4* blkb = (const uint4*)g_blkh + ((size_t)b * (LL + 1)) * 32 + lane;
    const float inv9 = 1.0f / 9.0f;

#pragma unroll
    for (int jj = 0; jj < 8; jj++) {
        int j = (w << 3) + jj;                // local cell 0..63
        int cell = (u << 7) + v0 + j;
        float4 A0 = make_float4(0.f, 0.f, 0.f, 0.f);   // channel 2*lane
        float4 A1 = make_float4(0.f, 0.f, 0.f, 0.f);   // channel 2*lane+1
        {   // taps 0..4
            uint4 t[5];
#pragma unroll
            for (int tap = 0; tap < 5; tap++)
                t[tap] = blkb[((size_t)tb[tap * LL + cell]) << 5];
#pragma unroll
            for (int tap = 0; tap < 5; tap++) {
                float2 f0 = __half22float2(*(__half2*)&t[tap].x);
                float2 f1 = __half22float2(*(__half2*)&t[tap].y);
                float2 f2 = __half22float2(*(__half2*)&t[tap].z);
                float2 f3 = __half22float2(*(__half2*)&t[tap].w);
                A0.x += f0.x; A0.y += f0.y; A0.z += f1.x; A0.w += f1.y;
                A1.x += f2.x; A1.y += f2.y; A1.z += f3.x; A1.w += f3.y;
            }
        }
        {   // taps 5..8
            uint4 t[4];
#pragma unroll
            for (int tap = 0; tap < 4; tap++)
                t[tap] = blkb[((size_t)tb[(5 + tap) * LL + cell]) << 5];
#pragma unroll
            for (int tap = 0; tap < 4; tap++) {
                float2 f0 = __half22float2(*(__half2*)&t[tap].x);
                float2 f1 = __half22float2(*(__half2*)&t[tap].y);
                float2 f2 = __half22float2(*(__half2*)&t[tap].z);
                float2 f3 = __half22float2(*(__half2*)&t[tap].w);
                A0.x += f0.x; A0.y += f0.y; A0.z += f1.x; A0.w += f1.y;
                A1.x += f2.x; A1.y += f2.y; A1.z += f3.x; A1.w += f3.y;
            }
        }
        int c0 = lane << 1;
        shh[(c0     ) * 65 + j] = __floats2half2_rn(A0.x * inv9, A0.y * inv9); // py0 c0
        shh[(64 + c0) * 65 + j] = __floats2half2_rn(A0.z * inv9, A0.w * inv9); // py1 c0
        shh[(c0 + 1 ) * 65 + j] = __floats2half2_rn(A1.x * inv9, A1.y * inv9); // py0 c0+1
        shh[(65 + c0) * 65 + j] = __floats2half2_rn(A1.z * inv9, A1.w * inv9); // py1 c0+1
    }
    __syncthreads();

    // Copy-out: warp per row (128 rows), half2->float2, coalesced 256B stores.
    for (int r = w; r < 128; r += 8) {
        int py = r >> 6;
        int c  = r & 63;
        float2* orow = (float2*)(out + (((size_t)(b * NC1 + c)) << 16)
                                 + ((2 * u + py) << 8) + (v0 << 1));
        const __half2* srow = shh + r * 65;
        orow[lane]      = __half22float2(srow[lane]);
        orow[lane + 32] = __half22float2(srow[lane + 32]);
    }
}

// ---------------------------------------------------------------------------
// Launch DAG (capture-legal fork/join):
//   s0: tab -> evTab ---------------- wait evB -> lv1 (solo) -> wait evG
//   s2: (wait evFork) -> blk (DRAM) -> evB
//   s3: (wait evFork) -> l2t (DRAM) -> wait evTab -> lv2g (L2) -> evG
// ---------------------------------------------------------------------------
extern "C" void kernel_launch(void* const* d_in, const int* in_sizes, int n_in,
                              void* d_out, int out_size) {
    const float* lv1 = nullptr;   // 8388608
    const float* lv2 = nullptr;   // 4194304
    const int*   hix = nullptr;   // 32768
    for (int i = 0; i < n_in; i++) {
        if (in_sizes[i] == 8388608)      lv1 = (const float*)d_in[i];
        else if (in_sizes[i] == 4194304) lv2 = (const float*)d_in[i];
        else if (in_sizes[i] == 32768)   hix = (const int*)d_in[i];
    }
    float* out = (float*)d_out;
    float* out1 = out + OUT_LV2_ELEMS;

    static cudaStream_t s2 = nullptr, s3 = nullptr;
    static cudaEvent_t evFork = nullptr, evTab = nullptr, evB = nullptr, evG = nullptr;
    if (!s2) {
        cudaStreamCreateWithFlags(&s2, cudaStreamNonBlocking);
        cudaStreamCreateWithFlags(&s3, cudaStreamNonBlocking);
        cudaEventCreateWithFlags(&evFork, cudaEventDisableTiming);
        cudaEventCreateWithFlags(&evTab,  cudaEventDisableTiming);
        cudaEventCreateWithFlags(&evB,    cudaEventDisableTiming);
        cudaEventCreateWithFlags(&evG,    cudaEventDisableTiming);
        cudaFuncSetAttribute(k_lv1, cudaFuncAttributeMaxDynamicSharedMemorySize, 33280);
    }

    cudaEventRecord(evFork, 0);
    cudaStreamWaitEvent(s2, evFork, 0);
    cudaStreamWaitEvent(s3, evFork, 0);

    k_blk<<<1024, 256, 0, s2>>>(lv1);          // s2: lv1 transpose (DRAM)
    cudaEventRecord(evB, s2);

    k_l2t<<<256, 256, 0, s3>>>(lv2);           // s3: lv2 transpose (DRAM)

    k_tab<<<32, 256>>>(hix);                   // s0: tap table
    cudaEventRecord(evTab, 0);
    cudaStreamWaitEvent(s3, evTab, 0);

    k_lv2g<<<512, 256, 0, s3>>>(out);          // s3: lv2 L2-gather (|| blk)
    cudaEventRecord(evG, s3);

    cudaStreamWaitEvent(0, evB, 0);
    k_lv1<<<512, 256, 33280>>>(out1);          // s0: lv1 L2-gather, solo
    cudaStreamWaitEvent(0, evG, 0);
}

// round 15
// speedup vs baseline: 1.0122x; 1.0122x over previous
#include <cuda_runtime.h>
#include <cuda_fp16.h>
#include <cstdint>

#define Hh 128
#define Ww 128
#define LL 16384          // H*W
#define NB 2
#define NC1 64
#define NC2 128
#define OUT_LV2_ELEMS 4194304
#define SENT 16384        // sentinel tap offset -> zero slot

// Scratch
__device__ unsigned short g_tab[NB * 9 * LL];                  // 576 KB tap offsets
__device__ uint2          g_blkh[(size_t)NB * (LL + 1) * 64];  // 16.8 MB lv1 half4 blocks
__device__ unsigned       g_l2h[(size_t)NB * (LL + 1) * 64];   // 8.4 MB lv2 pixel-major half2

// ---------------------------------------------------------------------------
// k_prep: ONE launch, three independent parts.
//   [0,1024):     blk  — lv1 space-to-depth fp16 transpose -> g_blkh
//   [1024,1280):  l2t  — lv2 pixel-major fp16 transpose    -> g_l2h
//   [1280,1312):  tab  — tap-offset table from hw          -> g_tab
// ---------------------------------------------------------------------------
__global__ void k_prep(const float* __restrict__ lv1,
                       const float* __restrict__ lv2,
                       const int*   __restrict__ hw) {
    extern __shared__ char smem_raw[];
    int bid = blockIdx.x;
    int tid = threadIdx.x;

    if (bid < 1024) {
        // ---- blk ----
        uint2* s2h = (uint2*)smem_raw;            // 64*33 uint2
        unsigned* sw = (unsigned*)s2h;
        int vt = bid & 3;
        int mh = (bid >> 2) & 127;
        int b  = bid >> 9;
        int v0 = vt << 5;
#pragma unroll
        for (int k = 0; k < 8; k++) {
            int j  = tid + (k << 8);
            int c  = j >> 5;
            int dy = (j >> 4) & 1;
            int x4 = j & 15;
            const float4 val = __ldcs((const float4*)(lv1 + (((size_t)(b * NC1 + c)) << 16)
                                                      + ((2 * mh + dy) << 8) + (v0 << 1) + (x4 << 2)));
            int vl0 = x4 << 1;
            __half2 h0 = __floats2half2_rn(val.x, val.y);
            __half2 h1 = __floats2half2_rn(val.z, val.w);
            sw[(c * 33 + vl0    ) * 2 + dy] = *(unsigned*)&h0;
            sw[(c * 33 + vl0 + 1) * 2 + dy] = *(unsigned*)&h1;
        }
        __syncthreads();
        uint2* dst = g_blkh + ((size_t)b * (LL + 1) + (mh << 7) + v0) * 64;
#pragma unroll
        for (int k = 0; k < 8; k++) {
            int j  = tid + (k << 8);
            int vl = j >> 6;
            int c  = j & 63;
            dst[(size_t)vl * 64 + c] = s2h[c * 33 + vl];
        }
    } else if (bid < 1280) {
        // ---- l2t ----
        __half* s = (__half*)smem_raw;            // 128*132 halves
        int lbid = bid - 1024;
        int b  = lbid >> 7;
        int pt = lbid & 127;
        int p0 = pt << 7;
#pragma unroll
        for (int k = 0; k < 16; k++) {
            int c  = (tid >> 5) + (k << 3);
            int x4 = tid & 31;
            const float4 v = __ldcs((const float4*)(lv2 + (((size_t)(b * NC2 + c)) << 14)
                                                    + p0 + (x4 << 2)));
            __half2 h0 = __floats2half2_rn(v.x, v.y);
            __half2 h1 = __floats2half2_rn(v.z, v.w);
            *(__half2*)&s[c * 132 + (x4 << 2)]     = h0;
            *(__half2*)&s[c * 132 + (x4 << 2) + 2] = h1;
        }
        __syncthreads();
        unsigned* dst = g_l2h + ((size_t)b * (LL + 1) + p0) * 64;
#pragma unroll
        for (int k = 0; k < 32; k++) {
            int px = (k << 2) + (tid >> 6);
            int wi = tid & 63;
            int c0 = wi << 1;
            __half2 hv = __halves2half2(s[c0 * 132 + px], s[(c0 + 1) * 132 + px]);
            dst[(size_t)px * 64 + wi] = *(unsigned*)&hv;
        }
    } else {
        // ---- tab ----
        __shared__ int s_or;
        int lbid = bid - 1280;                    // 0..31
        if (tid == 0) s_or = 0;
        __syncthreads();
        int acc = 0;
#pragma unroll
        for (int k = 0; k < 8; k++) acc |= hw[2 * (tid + (k << 8)) + 1];
        if (acc) atomicOr(&s_or, 1);
        __syncthreads();
        int stride = s_or ? 1 : 2;                // int32 vs int64 source

        if (lbid == 0 && tid < 128) {             // zero sentinel cells
            int b = tid >> 6, c = tid & 63;
            g_blkh[((size_t)b * (LL + 1) + LL) * 64 + c] = make_uint2(0u, 0u);
            g_l2h[((size_t)b * (LL + 1) + LL) * 64 + c] = 0u;
        }

#pragma unroll
        for (int k = 0; k < 4; k++) {
            int gp = (lbid << 10) + (k << 8) + tid;    // 0..32767
            int b  = gp >> 14;
            int p  = gp & (LL - 1);
            int y = p >> 7, x = p & 127;
            unsigned short* tp = g_tab + (size_t)b * 9 * LL;
#pragma unroll
            for (int dy = -1; dy <= 1; dy++) {
#pragma unroll
                for (int dx = -1; dx <= 1; dx++) {
                    int tap = (dy + 1) * 3 + (dx + 1);
                    int oy = y - dy, ox = x - dx;
                    unsigned short off = SENT;
                    if ((unsigned)oy < Hh && (unsigned)ox < Ww) {
                        int m  = hw[((b << 14) + (oy << 7) + ox) * stride];
                        int sr = (m >> 7)  + dy;
                        int sc = (m & 127) + dx;
                        if ((unsigned)sr < Hh && (unsigned)sc < Ww)
                            off = (unsigned short)((sr << 7) + sc);
                    }
                    tp[tap * LL + p] = off;
                }
            }
        }
    }
}

// ---------------------------------------------------------------------------
// k_gather: ONE launch, both gathers interleaved (even bid = lv1 cell tile,
// odd bid = lv2 pixel tile) so every SM carries a mix of the two access
// patterns and aggregate LDG MLP stays high.
// ---------------------------------------------------------------------------
__global__ void __launch_bounds__(256, 4) k_gather(float* __restrict__ out) {
    extern __shared__ char smem_raw[];
    int bid = blockIdx.x;                     // 1024
    int tid = threadIdx.x;
    int w    = tid >> 5;
    int lane = tid & 31;
    const float inv9 = 1.0f / 9.0f;
    int lbid = bid >> 1;                      // 0..511: (b, u|y, vtile|xtile)
    int vt   = lbid & 1;
    int uy   = (lbid >> 1) & 127;
    int b    = lbid >> 8;
    const unsigned short* tb = g_tab + (size_t)b * 9 * LL;

    if ((bid & 1) == 0) {
        // ---- lv1: warp-per-cell; lane = 2 channels; taps 5+4 ----
        __half2* shh = (__half2*)smem_raw;    // 128 x 65 half2
        int v0 = vt << 6;
        const uint4* blkb = (const uint4*)g_blkh + ((size_t)b * (LL + 1)) * 32 + lane;

#pragma unroll
        for (int jj = 0; jj < 8; jj++) {
            int j = (w << 3) + jj;            // local cell 0..63
            int cell = (uy << 7) + v0 + j;
            float4 A0 = make_float4(0.f, 0.f, 0.f, 0.f);
            float4 A1 = make_float4(0.f, 0.f, 0.f, 0.f);
            {   // taps 0..4
                uint4 t[5];
#pragma unroll
                for (int tap = 0; tap < 5; tap++)
                    t[tap] = blkb[((size_t)tb[tap * LL + cell]) << 5];
#pragma unroll
                for (int tap = 0; tap < 5; tap++) {
                    float2 f0 = __half22float2(*(__half2*)&t[tap].x);
                    float2 f1 = __half22float2(*(__half2*)&t[tap].y);
                    float2 f2 = __half22float2(*(__half2*)&t[tap].z);
                    float2 f3 = __half22float2(*(__half2*)&t[tap].w);
                    A0.x += f0.x; A0.y += f0.y; A0.z += f1.x; A0.w += f1.y;
                    A1.x += f2.x; A1.y += f2.y; A1.z += f3.x; A1.w += f3.y;
                }
            }
            {   // taps 5..8
                uint4 t[4];
#pragma unroll
                for (int tap = 0; tap < 4; tap++)
                    t[tap] = blkb[((size_t)tb[(5 + tap) * LL + cell]) << 5];
#pragma unroll
                for (int tap = 0; tap < 4; tap++) {
                    float2 f0 = __half22float2(*(__half2*)&t[tap].x);
                    float2 f1 = __half22float2(*(__half2*)&t[tap].y);
                    float2 f2 = __half22float2(*(__half2*)&t[tap].z);
                    float2 f3 = __half22float2(*(__half2*)&t[tap].w);
                    A0.x += f0.x; A0.y += f0.y; A0.z += f1.x; A0.w += f1.y;
                    A1.x += f2.x; A1.y += f2.y; A1.z += f3.x; A1.w += f3.y;
                }
            }
            int c0 = lane << 1;
            shh[(c0     ) * 65 + j] = __floats2half2_rn(A0.x * inv9, A0.y * inv9);
            shh[(64 + c0) * 65 + j] = __floats2half2_rn(A0.z * inv9, A0.w * inv9);
            shh[(c0 + 1 ) * 65 + j] = __floats2half2_rn(A1.x * inv9, A1.y * inv9);
            shh[(65 + c0) * 65 + j] = __floats2half2_rn(A1.z * inv9, A1.w * inv9);
        }
        __syncthreads();

        float* out1 = out + OUT_LV2_ELEMS;
        for (int r = w; r < 128; r += 8) {
            int py = r >> 6;
            int c  = r & 63;
            float2* orow = (float2*)(out1 + (((size_t)(b * NC1 + c)) << 16)
                                     + ((2 * uy + py) << 8) + (v0 << 1));
            const __half2* srow = shh + r * 65;
            orow[lane]      = __half22float2(srow[lane]);
            orow[lane + 32] = __half22float2(srow[lane + 32]);
        }
    } else {
        // ---- lv2: warp-per-pixel; lane = 4 channels; taps 5+4 ----
        __half2* s2 = (__half2*)smem_raw;     // 64 x 65 half2
        int p0 = (uy << 7) + (vt << 6);
        const uint2* src = (const uint2*)g_l2h + ((size_t)b * (LL + 1)) * 32 + lane;

#pragma unroll
        for (int jj = 0; jj < 8; jj++) {
            int px = (w << 3) + jj;           // local pixel 0..63
            int p  = p0 + px;
            float a0 = 0.f, a1 = 0.f, a2 = 0.f, a3 = 0.f;
            {   // taps 0..4
                uint2 t[5];
#pragma unroll
                for (int tap = 0; tap < 5; tap++)
                    t[tap] = src[((size_t)tb[tap * LL + p]) << 5];
#pragma unroll
                for (int tap = 0; tap < 5; tap++) {
                    float2 f0 = __half22float2(*(__half2*)&t[tap].x);
                    float2 f1 = __half22float2(*(__half2*)&t[tap].y);
                    a0 += f0.x; a1 += f0.y; a2 += f1.x; a3 += f1.y;
                }
            }
            {   // taps 5..8
                uint2 t[4];
#pragma unroll
                for (int tap = 0; tap < 4; tap++)
                    t[tap] = src[((size_t)tb[(5 + tap) * LL + p]) << 5];
#pragma unroll
                for (int tap = 0; tap < 4; tap++) {
                    float2 f0 = __half22float2(*(__half2*)&t[tap].x);
                    float2 f1 = __half22float2(*(__half2*)&t[tap].y);
                    a0 += f0.x; a1 += f0.y; a2 += f1.x; a3 += f1.y;
                }
            }
            s2[(2 * lane    ) * 65 + px] = __floats2half2_rn(a0 * inv9, a1 * inv9);
            s2[(2 * lane + 1) * 65 + px] = __floats2half2_rn(a2 * inv9, a3 * inv9);
        }
        __syncthreads();

        float* outb = out + (((size_t)b * NC2) << 14) + p0;
        for (int q = w; q < 64; q += 8) {
            float* r0 = outb + (((size_t)(q << 1)) << 14);
            float* r1 = r0 + LL;
            float2 f0 = __half22float2(s2[q * 65 + lane]);
            float2 f1 = __half22float2(s2[q * 65 + lane + 32]);
            r0[lane]      = f0.x;  r1[lane]      = f0.y;
            r0[lane + 32] = f1.x;  r1[lane + 32] = f1.y;
        }
    }
}

// ---------------------------------------------------------------------------
extern "C" void kernel_launch(void* const* d_in, const int* in_sizes, int n_in,
                              void* d_out, int out_size) {
    const float* lv1 = nullptr;   // 8388608
    const float* lv2 = nullptr;   // 4194304
    const int*   hix = nullptr;   // 32768
    for (int i = 0; i < n_in; i++) {
        if (in_sizes[i] == 8388608)      lv1 = (const float*)d_in[i];
        else if (in_sizes[i] == 4194304) lv2 = (const float*)d_in[i];
        else if (in_sizes[i] == 32768)   hix = (const int*)d_in[i];
    }
    float* out = (float*)d_out;

    static bool init = false;
    if (!init) {
        init = true;
        cudaFuncSetAttribute(k_prep,   cudaFuncAttributeMaxDynamicSharedMemorySize, 33792);
        cudaFuncSetAttribute(k_gather, cudaFuncAttributeMaxDynamicSharedMemorySize, 33280);
    }

    k_prep<<<1312, 256, 33792>>>(lv1, lv2, hix);
    k_gather<<<1024, 256, 33280>>>(out);
}

// round 16
// speedup vs baseline: 1.0443x; 1.0318x over previous
#include <cuda_runtime.h>
#include <cuda_fp16.h>
#include <cstdint>

#define Hh 128
#define Ww 128
#define LL 16384          // H*W
#define NB 2
#define NC1 64
#define NC2 128
#define OUT_LV2_ELEMS 4194304
#define SENT 16384        // sentinel tap offset -> zero slot

// Scratch
__device__ unsigned short g_tab[NB * 9 * LL];                  // 576 KB tap offsets
__device__ uint2          g_blkh[(size_t)NB * (LL + 1) * 64];  // 16.8 MB lv1 half4 blocks
__device__ unsigned       g_l2h[(size_t)NB * (LL + 1) * 64];   // 8.4 MB lv2 pixel-major half2

#define H2(u) (*(__half2*)&(u))

// ---------------------------------------------------------------------------
// k_prep: ONE launch, three independent parts (unchanged from R15).
//   [0,1024):     blk  — lv1 space-to-depth fp16 transpose -> g_blkh
//   [1024,1280):  l2t  — lv2 pixel-major fp16 transpose    -> g_l2h
//   [1280,1312):  tab  — tap-offset table from hw          -> g_tab
// ---------------------------------------------------------------------------
__global__ void k_prep(const float* __restrict__ lv1,
                       const float* __restrict__ lv2,
                       const int*   __restrict__ hw) {
    extern __shared__ char smem_raw[];
    int bid = blockIdx.x;
    int tid = threadIdx.x;

    if (bid < 1024) {
        // ---- blk ----
        uint2* s2h = (uint2*)smem_raw;            // 64*33 uint2
        unsigned* sw = (unsigned*)s2h;
        int vt = bid & 3;
        int mh = (bid >> 2) & 127;
        int b  = bid >> 9;
        int v0 = vt << 5;
#pragma unroll
        for (int k = 0; k < 8; k++) {
            int j  = tid + (k << 8);
            int c  = j >> 5;
            int dy = (j >> 4) & 1;
            int x4 = j & 15;
            const float4 val = __ldcs((const float4*)(lv1 + (((size_t)(b * NC1 + c)) << 16)
                                                      + ((2 * mh + dy) << 8) + (v0 << 1) + (x4 << 2)));
            int vl0 = x4 << 1;
            __half2 h0 = __floats2half2_rn(val.x, val.y);
            __half2 h1 = __floats2half2_rn(val.z, val.w);
            sw[(c * 33 + vl0    ) * 2 + dy] = *(unsigned*)&h0;
            sw[(c * 33 + vl0 + 1) * 2 + dy] = *(unsigned*)&h1;
        }
        __syncthreads();
        uint2* dst = g_blkh + ((size_t)b * (LL + 1) + (mh << 7) + v0) * 64;
#pragma unroll
        for (int k = 0; k < 8; k++) {
            int j  = tid + (k << 8);
            int vl = j >> 6;
            int c  = j & 63;
            dst[(size_t)vl * 64 + c] = s2h[c * 33 + vl];
        }
    } else if (bid < 1280) {
        // ---- l2t ----
        __half* s = (__half*)smem_raw;            // 128*132 halves
        int lbid = bid - 1024;
        int b  = lbid >> 7;
        int pt = lbid & 127;
        int p0 = pt << 7;
#pragma unroll
        for (int k = 0; k < 16; k++) {
            int c  = (tid >> 5) + (k << 3);
            int x4 = tid & 31;
            const float4 v = __ldcs((const float4*)(lv2 + (((size_t)(b * NC2 + c)) << 14)
                                                    + p0 + (x4 << 2)));
            __half2 h0 = __floats2half2_rn(v.x, v.y);
            __half2 h1 = __floats2half2_rn(v.z, v.w);
            *(__half2*)&s[c * 132 + (x4 << 2)]     = h0;
            *(__half2*)&s[c * 132 + (x4 << 2) + 2] = h1;
        }
        __syncthreads();
        unsigned* dst = g_l2h + ((size_t)b * (LL + 1) + p0) * 64;
#pragma unroll
        for (int k = 0; k < 32; k++) {
            int px = (k << 2) + (tid >> 6);
            int wi = tid & 63;
            int c0 = wi << 1;
            __half2 hv = __halves2half2(s[c0 * 132 + px], s[(c0 + 1) * 132 + px]);
            dst[(size_t)px * 64 + wi] = *(unsigned*)&hv;
        }
    } else {
        // ---- tab ----
        __shared__ int s_or;
        int lbid = bid - 1280;                    // 0..31
        if (tid == 0) s_or = 0;
        __syncthreads();
        int acc = 0;
#pragma unroll
        for (int k = 0; k < 8; k++) acc |= hw[2 * (tid + (k << 8)) + 1];
        if (acc) atomicOr(&s_or, 1);
        __syncthreads();
        int stride = s_or ? 1 : 2;                // int32 vs int64 source

        if (lbid == 0 && tid < 128) {             // zero sentinel cells
            int b = tid >> 6, c = tid & 63;
            g_blkh[((size_t)b * (LL + 1) + LL) * 64 + c] = make_uint2(0u, 0u);
            g_l2h[((size_t)b * (LL + 1) + LL) * 64 + c] = 0u;
        }

#pragma unroll
        for (int k = 0; k < 4; k++) {
            int gp = (lbid << 10) + (k << 8) + tid;    // 0..32767
            int b  = gp >> 14;
            int p  = gp & (LL - 1);
            int y = p >> 7, x = p & 127;
            unsigned short* tp = g_tab + (size_t)b * 9 * LL;
#pragma unroll
            for (int dy = -1; dy <= 1; dy++) {
#pragma unroll
                for (int dx = -1; dx <= 1; dx++) {
                    int tap = (dy + 1) * 3 + (dx + 1);
                    int oy = y - dy, ox = x - dx;
                    unsigned short off = SENT;
                    if ((unsigned)oy < Hh && (unsigned)ox < Ww) {
                        int m  = hw[((b << 14) + (oy << 7) + ox) * stride];
                        int sr = (m >> 7)  + dy;
                        int sc = (m & 127) + dx;
                        if ((unsigned)sr < Hh && (unsigned)sc < Ww)
                            off = (unsigned short)((sr << 7) + sc);
                    }
                    tp[tap * LL + p] = off;
                }
            }
        }
    }
}

// ---------------------------------------------------------------------------
// 9-way half2 sum tree
// ---------------------------------------------------------------------------
__device__ __forceinline__ __half2 hsum9(__half2 a, __half2 b, __half2 c,
                                         __half2 d, __half2 e, __half2 f,
                                         __half2 g, __half2 h, __half2 i) {
    __half2 s01 = __hadd2(a, b), s23 = __hadd2(c, d);
    __half2 s45 = __hadd2(e, f), s67 = __hadd2(g, h);
    return __hadd2(__hadd2(__hadd2(s01, s23), __hadd2(s45, s67)), i);
}

// ---------------------------------------------------------------------------
// k_gather: ONE launch, both gathers interleaved (even bid = lv1 cell tile,
// odd bid = lv2 pixel tile). HALF2 accumulation: taps summed with HADD2
// directly on loaded words (no per-tap conversions); inv9 + fp32 conversion
// deferred to the copy-out phase where h2f already happens.
// ---------------------------------------------------------------------------
__global__ void __launch_bounds__(256, 4) k_gather(float* __restrict__ out) {
    extern __shared__ char smem_raw[];
    int bid = blockIdx.x;                     // 1024
    int tid = threadIdx.x;
    int w    = tid >> 5;
    int lane = tid & 31;
    const float inv9 = 1.0f / 9.0f;
    int lbid = bid >> 1;                      // 0..511: (b, u|y, vtile|xtile)
    int vt   = lbid & 1;
    int uy   = (lbid >> 1) & 127;
    int b    = lbid >> 8;
    const unsigned short* tb = g_tab + (size_t)b * 9 * LL;

    if ((bid & 1) == 0) {
        // ---- lv1: warp-per-cell; lane = 2 channels; all 9 taps in flight ----
        __half2* shh = (__half2*)smem_raw;    // 128 x 65 half2
        int v0 = vt << 6;
        const uint4* blkb = (const uint4*)g_blkh + ((size_t)b * (LL + 1)) * 32 + lane;

#pragma unroll
        for (int jj = 0; jj < 8; jj++) {
            int j = (w << 3) + jj;            // local cell 0..63
            int cell = (uy << 7) + v0 + j;
            uint4 t[9];
#pragma unroll
            for (int tap = 0; tap < 9; tap++)
                t[tap] = blkb[((size_t)tb[tap * LL + cell]) << 5];
            __half2 a0 = hsum9(H2(t[0].x), H2(t[1].x), H2(t[2].x), H2(t[3].x),
                               H2(t[4].x), H2(t[5].x), H2(t[6].x), H2(t[7].x), H2(t[8].x));
            __half2 a1 = hsum9(H2(t[0].y), H2(t[1].y), H2(t[2].y), H2(t[3].y),
                               H2(t[4].y), H2(t[5].y), H2(t[6].y), H2(t[7].y), H2(t[8].y));
            __half2 a2 = hsum9(H2(t[0].z), H2(t[1].z), H2(t[2].z), H2(t[3].z),
                               H2(t[4].z), H2(t[5].z), H2(t[6].z), H2(t[7].z), H2(t[8].z));
            __half2 a3 = hsum9(H2(t[0].w), H2(t[1].w), H2(t[2].w), H2(t[3].w),
                               H2(t[4].w), H2(t[5].w), H2(t[6].w), H2(t[7].w), H2(t[8].w));
            int c0 = lane << 1;
            shh[(c0     ) * 65 + j] = a0;     // py0 c0 (raw sum; inv9 at copy-out)
            shh[(64 + c0) * 65 + j] = a1;     // py1 c0
            shh[(c0 + 1 ) * 65 + j] = a2;     // py0 c0+1
            shh[(65 + c0) * 65 + j] = a3;     // py1 c0+1
        }
        __syncthreads();

        float* out1 = out + OUT_LV2_ELEMS;
        for (int r = w; r < 128; r += 8) {
            int py = r >> 6;
            int c  = r & 63;
            float2* orow = (float2*)(out1 + (((size_t)(b * NC1 + c)) << 16)
                                     + ((2 * uy + py) << 8) + (v0 << 1));
            const __half2* srow = shh + r * 65;
            float2 f0 = __half22float2(srow[lane]);
            float2 f1 = __half22float2(srow[lane + 32]);
            orow[lane]      = make_float2(f0.x * inv9, f0.y * inv9);
            orow[lane + 32] = make_float2(f1.x * inv9, f1.y * inv9);
        }
    } else {
        // ---- lv2: warp-per-pixel; lane = 4 channels; all 9 taps in flight ----
        __half2* s2 = (__half2*)smem_raw;     // 64 x 65 half2
        int p0 = (uy << 7) + (vt << 6);
        const uint2* src = (const uint2*)g_l2h + ((size_t)b * (LL + 1)) * 32 + lane;

#pragma unroll
        for (int jj = 0; jj < 8; jj++) {
            int px = (w << 3) + jj;           // local pixel 0..63
            int p  = p0 + px;
            uint2 t[9];
#pragma unroll
            for (int tap = 0; tap < 9; tap++)
                t[tap] = src[((size_t)tb[tap * LL + p]) << 5];
            __half2 a0 = hsum9(H2(t[0].x), H2(t[1].x), H2(t[2].x), H2(t[3].x),
                               H2(t[4].x), H2(t[5].x), H2(t[6].x), H2(t[7].x), H2(t[8].x));
            __half2 a1 = hsum9(H2(t[0].y), H2(t[1].y), H2(t[2].y), H2(t[3].y),
                               H2(t[4].y), H2(t[5].y), H2(t[6].y), H2(t[7].y), H2(t[8].y));
            s2[(2 * lane    ) * 65 + px] = a0;
            s2[(2 * lane + 1) * 65 + px] = a1;
        }
        __syncthreads();

        float* outb = out + (((size_t)b * NC2) << 14) + p0;
        for (int q = w; q < 64; q += 8) {
            float* r0 = outb + (((size_t)(q << 1)) << 14);
            float* r1 = r0 + LL;
            float2 f0 = __half22float2(s2[q * 65 + lane]);
            float2 f1 = __half22float2(s2[q * 65 + lane + 32]);
            r0[lane]      = f0.x * inv9;  r1[lane]      = f0.y * inv9;
            r0[lane + 32] = f1.x * inv9;  r1[lane + 32] = f1.y * inv9;
        }
    }
}

// ---------------------------------------------------------------------------
extern "C" void kernel_launch(void* const* d_in, const int* in_sizes, int n_in,
                              void* d_out, int out_size) {
    const float* lv1 = nullptr;   // 8388608
    const float* lv2 = nullptr;   // 4194304
    const int*   hix = nullptr;   // 32768
    for (int i = 0; i < n_in; i++) {
        if (in_sizes[i] == 8388608)      lv1 = (const float*)d_in[i];
        else if (in_sizes[i] == 4194304) lv2 = (const float*)d_in[i];
        else if (in_sizes[i] == 32768)   hix = (const int*)d_in[i];
    }
    float* out = (float*)d_out;

    static bool init = false;
    if (!init) {
        init = true;
        cudaFuncSetAttribute(k_prep,   cudaFuncAttributeMaxDynamicSharedMemorySize, 33792);
        cudaFuncSetAttribute(k_gather, cudaFuncAttributeMaxDynamicSharedMemorySize, 33280);
    }

    k_prep<<<1312, 256, 33792>>>(lv1, lv2, hix);
    k_gather<<<1024, 256, 33280>>>(out);
}